// round 6
// baseline (speedup 1.0000x reference)
#include <cuda_runtime.h>
#include <math.h>

#define BS 32
#define NA 8400
#define NC 80
#define NB 64
#define TOPKK 13
#define CAP 512

#define OFF_LABELS 0
#define OFF_BBOX   (BS*NA)
#define OFF_SCORES (BS*NA + BS*NA*4)
#define OFF_FG     (OFF_SCORES + BS*NA*NC)
#define OFF_TGI    (OFF_FG + BS*NA)

// ---------------- scratch ----------------
__device__ unsigned long long g_maskbits[BS*NA];  // bit g = mask_pos(g,a) pre-dedup
__device__ unsigned long long g_pack   [BS*NA];   // max over valid g: (ov_bits<<8)|(63-g)
__device__ unsigned long long g_packsel[BS*NA];   // same pack, topk-selected pairs only
__device__ int                g_cnt [BS*NB];      // per-row candidate counts
__device__ unsigned long long g_key [BS*NB*CAP];  // (al_bits<<32)|(NA-1-a)
__device__ float              g_cov [BS*NB*CAP];  // candidate overlap
__device__ float              g_posalign[BS*NB];
__device__ float              g_posover [BS*NB];
__device__ int                g_tgi [BS*NA];
__device__ unsigned char      g_fgb [BS*NA];
__device__ float              g_amax[BS*NA];
__device__ int                g_lab [BS*NA];

// ---------------- K_clear: only the atomic accumulators ----------------
__global__ void k_clear()
{
    int i = blockIdx.x * blockDim.x + threadIdx.x;
    if (i < BS*NB) { g_cnt[i] = 0; g_posalign[i] = 0.f; g_posover[i] = 0.f; }
}

// ---------------- K_main: per-(b,anchor) over valid gts + fused score zero-fill ----------------
__global__ __launch_bounds__(256) void k_main(
    const float*  __restrict__ pd_scores,
    const float4* __restrict__ pd_bboxes,
    const float2* __restrict__ anc,
    const int*    __restrict__ gt_labels,
    const float4* __restrict__ gt_bboxes,
    const float*  __restrict__ mask_gt,
    float* __restrict__ out)
{
    int b = blockIdx.y;
    int a0 = blockIdx.x * 256;

    // fused zero-fill of this block's slice of target_scores: stores drain
    // through L2/DRAM while the compute loop below runs (DRAM idle otherwise)
    {
        int cnt = min(256, NA - a0);
        float4* dst = (float4*)(out + OFF_SCORES + ((long)b*NA + a0) * NC);
        int n4 = cnt * NC / 4;
        float4 z = make_float4(0.f,0.f,0.f,0.f);
        for (int i = threadIdx.x; i < n4; i += 256) dst[i] = z;
    }

    __shared__ float4 s_box[NB];
    __shared__ float  s_at1[NB], s_a1[NB];
    __shared__ int    s_lbl[NB], s_gi[NB];
    __shared__ int    s_nv;
    __shared__ float4        t_box[NB];
    __shared__ float         t_at1[NB], t_a1[NB];
    __shared__ int           t_lbl[NB];
    __shared__ unsigned char t_v[NB];

    if (threadIdx.x < NB) {
        int g = threadIdx.x;
        float4 G = gt_bboxes[b*NB + g];
        t_box[g] = G;
        t_lbl[g] = gt_labels[b*NB + g];
        t_v[g]   = mask_gt[b*NB + g] > 0.f;
        float w1 = G.z - G.x, h1 = G.w - G.y + 1e-7f;
        t_at1[g] = atanf(w1 / h1);
        t_a1[g]  = w1 * h1;
    }
    __syncthreads();
    if (threadIdx.x == 0) {   // deterministic serial compaction of valid gts
        int nv = 0;
        for (int g = 0; g < NB; ++g) if (t_v[g]) {
            s_box[nv] = t_box[g]; s_at1[nv] = t_at1[g]; s_a1[nv] = t_a1[g];
            s_lbl[nv] = t_lbl[g]; s_gi[nv] = g; nv++;
        }
        s_nv = nv;
    }
    __syncthreads();

    int a = a0 + threadIdx.x;
    if (a >= NA) return;
    int ba = b*NA + a;

    // zero the per-anchor atomic targets for k_top (replaces bulk clear kernel)
    g_maskbits[ba] = 0ull;
    g_packsel[ba]  = 0ull;

    float2 ap = anc[a];
    float4 p  = pd_bboxes[ba];
    float w2 = p.z - p.x, h2 = p.w - p.y + 1e-7f;
    float at2 = atanf(w2 / h2);
    float wh2 = w2 * h2;
    const float* sc = pd_scores + (long)ba * NC;

    unsigned long long packall = 0;
    int nv = s_nv;

    for (int j = 0; j < nv; ++j) {
        float4 G = s_box[j];
        // equivalent to deltas.min > 1e-9 at these magnitudes (fp32 spacing >> 1e-9)
        int inb = (ap.x > G.x) & (ap.y > G.y) & (ap.x < G.z) & (ap.y < G.w);
        if (!inb) continue;

        float iw = fminf(G.z, p.z) - fmaxf(G.x, p.x);
        float ih = fminf(G.w, p.w) - fmaxf(G.y, p.y);
        float inter = fmaxf(iw, 0.f) * fmaxf(ih, 0.f);
        float uni = s_a1[j] + wh2 - inter + 1e-7f;
        float iou = inter / uni;
        float cw = fmaxf(G.z, p.z) - fminf(G.x, p.x);
        float ch = fmaxf(G.w, p.w) - fminf(G.y, p.y);
        float c2 = cw*cw + ch*ch + 1e-7f;
        float dx = p.x + p.z - G.x - G.z;
        float dy = p.y + p.w - G.y - G.w;
        float rho2 = (dx*dx + dy*dy) * 0.25f;
        float dd = at2 - s_at1[j];
        float v = 0.4052847345693511f * dd * dd;   // 4/pi^2
        float alpha = v / (v - iou + (1.0f + 1e-7f));
        float ci = iou - (rho2 / c2 + v * alpha);
        float ov = fmaxf(ci, 0.f);
        if (ov <= 0.f) continue;

        int g = s_gi[j];
        // per-anchor argmax over g (ties -> lowest g, like jnp.argmax)
        unsigned long long pk =
            ((unsigned long long)__float_as_uint(ov) << 8) | (unsigned)(63 - g);
        packall = max(packall, pk);

        float s  = sc[s_lbl[j]];
        float o2 = ov * ov;
        float al = s * o2 * o2 * o2;   // score^1 * ov^6
        if (al > 0.f) {
            int row = b * NB + g;
            int slot = atomicAdd(&g_cnt[row], 1);
            if (slot < CAP) {
                g_key[(long)row*CAP + slot] =
                    ((unsigned long long)__float_as_uint(al) << 32) | (unsigned)(NA - 1 - a);
                g_cov[(long)row*CAP + slot] = ov;
            }
        }
    }
    g_pack[ba] = packall;
}

// ---------------- K_top: per-row top-13 over compacted candidates ----------------
__global__ void k_top(
    const float2* __restrict__ anc,
    const float4* __restrict__ gt_bboxes,
    const float*  __restrict__ mask_gt)
{
    int g = blockIdx.x, b = blockIdx.y;
    int row = b*NB + g;
    if (mask_gt[row] <= 0.f) return;   // masked rows killed by cnt>1 in ref
    int lane = threadIdx.x;

    __shared__ unsigned long long s_key[CAP];
    __shared__ float s_cov[CAP];
    __shared__ int   s_ca[CAP];

    int C = min(g_cnt[row], CAP);
    for (int j = lane; j < C; j += 32) {
        unsigned long long k = g_key[(long)row*CAP + j];
        s_key[j] = k;
        s_cov[j] = g_cov[(long)row*CAP + j];
        s_ca[j]  = NA - 1 - (int)(k & 0xffffffffull);
    }
    __syncwarp();

    int npos = min(C, TOPKK);
    for (int it = 0; it < npos; ++it) {
        unsigned long long bk = 0; int bj = -1;
        for (int j = lane; j < C; j += 32) {
            unsigned long long k = s_key[j];
            if (k > bk) { bk = k; bj = j; }
        }
        #pragma unroll
        for (int off = 16; off; off >>= 1) {
            unsigned long long kk = __shfl_down_sync(0xffffffffu, bk, off);
            int jj = __shfl_down_sync(0xffffffffu, bj, off);
            if (kk > bk) { bk = kk; bj = jj; }
        }
        bj = __shfl_sync(0xffffffffu, bj, 0);
        if (lane == 0) {
            int a = s_ca[bj];
            atomicOr(&g_maskbits[b*NA + a], 1ull << g);  // positives are in-box
            unsigned long long pk =
                ((unsigned long long)__float_as_uint(s_cov[bj]) << 8) | (unsigned)(63 - g);
            atomicMax(&g_packsel[b*NA + a], pk);
            s_key[bj] = 0;
        }
        __syncwarp();
    }

    // fewer than 13 positives: ref fills with lowest-index zero entries
    if (lane == 0 && C < TOPKK) {
        float4 G = gt_bboxes[row];
        int rem = TOPKK - C;
        for (int a = 0; rem > 0 && a < NA; ++a) {
            bool member = false;
            for (int j = 0; j < C; ++j) if (s_ca[j] == a) { member = true; break; }
            if (member) continue;
            rem--;                                  // slot consumed by this zero entry
            float2 ap = anc[a];
            int inb = (ap.x > G.x) & (ap.y > G.y) & (ap.x < G.z) & (ap.y < G.w);
            if (inb)                                // mask only if in-box (ov=0 -> no packsel)
                atomicOr(&g_maskbits[b*NA + a], 1ull << g);
        }
    }
}

// ---------------- K_assign: dedup + targets + pos-max ----------------
__global__ __launch_bounds__(256) void k_assign(
    const float*  __restrict__ pd_scores,
    const int*    __restrict__ gt_labels,
    const float4* __restrict__ gt_bboxes,
    float* __restrict__ out)
{
    int b = blockIdx.y;
    __shared__ int s_lbl[NB];
    if (threadIdx.x < NB) s_lbl[threadIdx.x] = gt_labels[b*NB + threadIdx.x];
    __syncthreads();

    int a = blockIdx.x * 256 + threadIdx.x;
    if (a >= NA) return;
    int ba = b*NA + a;

    unsigned long long m = g_maskbits[ba];
    int fg = __popcll(m);
    int tgi = 0; float ovv = 0.f;
    if (fg > 1) {               // multi-assigned -> argmax over masked overlaps (all g)
        unsigned long long pk = g_pack[ba];
        if (pk) {
            tgi = 63 - (int)(pk & 63ull);
            ovv = __uint_as_float((unsigned)(pk >> 8));
        }
    } else if (fg == 1) {
        tgi = __ffsll((long long)m) - 1;
        unsigned long long ps = g_packsel[ba];
        ovv = __uint_as_float((unsigned)(ps >> 8));
    }
    bool active = fg > 0;

    float am = 0.f;
    if (active && ovv > 0.f) {
        float s = pd_scores[(long)ba * NC + s_lbl[tgi]];
        float o2 = ovv * ovv;
        am = s * o2 * o2 * o2;   // identical recompute of align metric
    }
    if (active) {   // non-negative floats: int-compare atomicMax is exact
        atomicMax((int*)&g_posalign[b*NB + tgi], __float_as_int(am));
        atomicMax((int*)&g_posover [b*NB + tgi], __float_as_int(ovv));
    }

    int lab = max(s_lbl[tgi], 0);
    g_tgi[ba] = tgi; g_fgb[ba] = active; g_amax[ba] = am; g_lab[ba] = lab;

    out[OFF_LABELS + ba] = (float)lab;
    ((float4*)(out + OFF_BBOX))[ba] = gt_bboxes[b*NB + tgi];
    out[OFF_FG  + ba] = active ? 1.f : 0.f;
    out[OFF_TGI + ba] = (float)tgi;
}

// ---------------- K_scores: scatter one-hot * norm (region pre-zeroed in k_main) ----------------
__global__ void k_scores(float* __restrict__ out)
{
    int ba = blockIdx.x * blockDim.x + threadIdx.x;
    if (ba >= BS*NA) return;
    if (!g_fgb[ba]) return;
    int b = ba / NA;
    int tgi = g_tgi[ba];
    float pa = g_posalign[b*NB + tgi];
    float po = g_posover [b*NB + tgi];
    out[OFF_SCORES + (long)ba * NC + g_lab[ba]] = (g_amax[ba] * po) / (pa + 1e-9f);
}

// ---------------- launch ----------------
extern "C" void kernel_launch(void* const* d_in, const int* in_sizes, int n_in,
                              void* d_out, int out_size)
{
    const float*  pd_scores = (const float*) d_in[0];
    const float4* pd_bboxes = (const float4*)d_in[1];
    const float2* anc       = (const float2*)d_in[2];
    const int*    gt_labels = (const int*)   d_in[3];
    const float4* gt_bboxes = (const float4*)d_in[4];
    const float*  mask_gt   = (const float*) d_in[5];
    float* out = (float*)d_out;

    k_clear<<<(BS*NB + 255)/256, 256>>>();

    dim3 gmain((NA + 255)/256, BS);
    k_main<<<gmain, 256>>>(pd_scores, pd_bboxes, anc, gt_labels, gt_bboxes, mask_gt, out);

    dim3 gtop(NB, BS);
    k_top<<<gtop, 32>>>(anc, gt_bboxes, mask_gt);

    dim3 gassign((NA + 255)/256, BS);
    k_assign<<<gassign, 256>>>(pd_scores, gt_labels, gt_bboxes, out);

    k_scores<<<(BS*NA + 255)/256, 256>>>(out);
}

// round 9
// speedup vs baseline: 1.0846x; 1.0846x over previous
#include <cuda_runtime.h>
#include <math.h>

#define BS 32
#define NA 8400
#define NC 80
#define NB 64
#define TOPKK 13
#define CAP 512

#define OFF_LABELS 0
#define OFF_BBOX   (BS*NA)
#define OFF_SCORES (BS*NA + BS*NA*4)
#define OFF_FG     (OFF_SCORES + BS*NA*NC)
#define OFF_TGI    (OFF_FG + BS*NA)

// ---------------- scratch (module-load zero-initialized; each consumer re-zeroes) ----------------
__device__ unsigned long long g_maskbits[BS*NA];  // bit g = mask_pos(g,a) pre-dedup
__device__ unsigned long long g_pack   [BS*NA];   // max over valid g: (ov_bits<<8)|(63-g)
__device__ unsigned long long g_packsel[BS*NA];   // same pack, topk-selected pairs only
__device__ int                g_cnt [BS*NB];      // per-row candidate counts (zeroed by k_top)
__device__ unsigned long long g_key [BS*NB*CAP];  // (al_bits<<32)|(NA-1-a)
__device__ float              g_cov [BS*NB*CAP];  // candidate overlap
__device__ float              g_posalign[BS*NB];  // zeroed by k_main block(0,0)
__device__ float              g_posover [BS*NB];
__device__ int                g_tgi [BS*NA];
__device__ unsigned char      g_fgb [BS*NA];
__device__ float              g_amax[BS*NA];
__device__ int                g_lab [BS*NA];

__device__ __forceinline__ bool ap_inb(float4 G, float2 ap)
{
    return ap.x > G.x && ap.y > G.y && ap.x < G.z && ap.y < G.w;
}

// ---------------- K_main: per-(b,anchor); bitmask pass then sparse CIoU ----------------
__global__ __launch_bounds__(256) void k_main(
    const float*  __restrict__ pd_scores,
    const float4* __restrict__ pd_bboxes,
    const float2* __restrict__ anc,
    const int*    __restrict__ gt_labels,
    const float4* __restrict__ gt_bboxes,
    const float*  __restrict__ mask_gt)
{
    int b = blockIdx.y;

    // designated block zeroes the pos-max accumulators for k_assign (a later kernel)
    if (blockIdx.x == 0 && b == 0) {
        for (int i = threadIdx.x; i < BS*NB; i += 256) {
            g_posalign[i] = 0.f; g_posover[i] = 0.f;
        }
    }

    __shared__ float4 s_box[NB];
    __shared__ float  s_at1[NB], s_a1[NB];
    __shared__ int    s_lbl[NB], s_gi[NB];
    __shared__ int    s_nv;
    __shared__ float4        t_box[NB];
    __shared__ float         t_at1[NB], t_a1[NB];
    __shared__ int           t_lbl[NB];
    __shared__ unsigned char t_v[NB];

    if (threadIdx.x < NB) {
        int g = threadIdx.x;
        float4 G = gt_bboxes[b*NB + g];
        t_box[g] = G;
        t_lbl[g] = gt_labels[b*NB + g];
        t_v[g]   = mask_gt[b*NB + g] > 0.f;
        float w1 = G.z - G.x, h1 = G.w - G.y + 1e-7f;
        t_at1[g] = atanf(w1 / h1);
        t_a1[g]  = w1 * h1;
    }
    __syncthreads();
    if (threadIdx.x == 0) {   // deterministic serial compaction of valid gts
        int nv = 0;
        for (int g = 0; g < NB; ++g) if (t_v[g]) {
            s_box[nv] = t_box[g]; s_at1[nv] = t_at1[g]; s_a1[nv] = t_a1[g];
            s_lbl[nv] = t_lbl[g]; s_gi[nv] = g; nv++;
        }
        s_nv = nv;
    }
    __syncthreads();

    int a = blockIdx.x * 256 + threadIdx.x;
    if (a >= NA) return;
    int ba = b*NA + a;

    // zero the per-anchor atomic targets for k_top (replaces a bulk clear kernel)
    g_maskbits[ba] = 0ull;
    g_packsel[ba]  = 0ull;

    float2 ap = anc[a];
    float4 p  = pd_bboxes[ba];
    float w2 = p.z - p.x, h2 = p.w - p.y + 1e-7f;
    float at2 = atanf(w2 / h2);
    float wh2 = w2 * h2;
    const float* sc = pd_scores + (long)ba * NC;

    int nv = s_nv;

    // Phase 1: cheap in-box bitmask (equiv. to deltas.min > 1e-9 at these magnitudes)
    unsigned long long inbm = 0ull;
    for (int j = 0; j < nv; ++j) {
        float4 G = s_box[j];
        if (ap.x > G.x && ap.y > G.y && ap.x < G.z && ap.y < G.w)
            inbm |= 1ull << j;
    }

    // Phase 2: heavy CIoU only for set bits (warp trip = max popcount ~ 3-4)
    unsigned long long packall = 0;
    while (inbm) {
        int j = __ffsll((long long)inbm) - 1;
        inbm &= inbm - 1;

        float4 G = s_box[j];
        float iw = fminf(G.z, p.z) - fmaxf(G.x, p.x);
        float ih = fminf(G.w, p.w) - fmaxf(G.y, p.y);
        float inter = fmaxf(iw, 0.f) * fmaxf(ih, 0.f);
        float uni = s_a1[j] + wh2 - inter + 1e-7f;
        float iou = inter / uni;
        float cw = fmaxf(G.z, p.z) - fminf(G.x, p.x);
        float ch = fmaxf(G.w, p.w) - fminf(G.y, p.y);
        float c2 = cw*cw + ch*ch + 1e-7f;
        float dx = p.x + p.z - G.x - G.z;
        float dy = p.y + p.w - G.y - G.w;
        float rho2 = (dx*dx + dy*dy) * 0.25f;
        float dd = at2 - s_at1[j];
        float v = 0.4052847345693511f * dd * dd;   // 4/pi^2
        float alpha = v / (v - iou + (1.0f + 1e-7f));
        float ci = iou - (rho2 / c2 + v * alpha);
        float ov = fmaxf(ci, 0.f);
        if (ov <= 0.f) continue;

        int g = s_gi[j];
        // per-anchor argmax over g (ties -> lowest g, like jnp.argmax)
        unsigned long long pk =
            ((unsigned long long)__float_as_uint(ov) << 8) | (unsigned)(63 - g);
        packall = max(packall, pk);

        float s  = sc[s_lbl[j]];
        float o2 = ov * ov;
        float al = s * o2 * o2 * o2;   // score^1 * ov^6
        if (al > 0.f) {
            int row = b * NB + g;
            int slot = atomicAdd(&g_cnt[row], 1);
            if (slot < CAP) {
                g_key[(long)row*CAP + slot] =
                    ((unsigned long long)__float_as_uint(al) << 32) | (unsigned)(NA - 1 - a);
                g_cov[(long)row*CAP + slot] = ov;
            }
        }
    }
    g_pack[ba] = packall;
}

// ---------------- K_top: per-row top-13 over compacted candidates ----------------
__global__ void k_top(
    const float2* __restrict__ anc,
    const float4* __restrict__ gt_bboxes,
    const float*  __restrict__ mask_gt)
{
    int g = blockIdx.x, b = blockIdx.y;
    int row = b*NB + g;
    if (mask_gt[row] <= 0.f) return;   // masked rows push no candidates; g_cnt stays 0
    int lane = threadIdx.x;

    __shared__ unsigned long long s_key[CAP];
    __shared__ float s_cov[CAP];
    __shared__ int   s_ca[CAP];

    int C = min(g_cnt[row], CAP);
    if (lane == 0) g_cnt[row] = 0;     // re-arm for next call (selection uses C)
    for (int j = lane; j < C; j += 32) {
        unsigned long long k = g_key[(long)row*CAP + j];
        s_key[j] = k;
        s_cov[j] = g_cov[(long)row*CAP + j];
        s_ca[j]  = NA - 1 - (int)(k & 0xffffffffull);
    }
    __syncwarp();

    int npos = min(C, TOPKK);
    for (int it = 0; it < npos; ++it) {
        unsigned long long bk = 0; int bj = -1;
        for (int j = lane; j < C; j += 32) {
            unsigned long long k = s_key[j];
            if (k > bk) { bk = k; bj = j; }
        }
        #pragma unroll
        for (int off = 16; off; off >>= 1) {
            unsigned long long kk = __shfl_down_sync(0xffffffffu, bk, off);
            int jj = __shfl_down_sync(0xffffffffu, bj, off);
            if (kk > bk) { bk = kk; bj = jj; }
        }
        bj = __shfl_sync(0xffffffffu, bj, 0);
        if (lane == 0) {
            int a = s_ca[bj];
            atomicOr(&g_maskbits[b*NA + a], 1ull << g);  // positives are in-box
            unsigned long long pk =
                ((unsigned long long)__float_as_uint(s_cov[bj]) << 8) | (unsigned)(63 - g);
            atomicMax(&g_packsel[b*NA + a], pk);
            s_key[bj] = 0;
        }
        __syncwarp();
    }

    // fewer than 13 positives: ref fills with lowest-index zero entries
    if (lane == 0 && C < TOPKK) {
        float4 G = gt_bboxes[row];
        int rem = TOPKK - C;
        for (int a = 0; rem > 0 && a < NA; ++a) {
            bool member = false;
            for (int j = 0; j < C; ++j) if (s_ca[j] == a) { member = true; break; }
            if (member) continue;
            rem--;                                  // slot consumed by this zero entry
            if (ap_inb(G, anc[a]))                  // mask only if in-box (ov=0 -> no packsel)
                atomicOr(&g_maskbits[b*NA + a], 1ull << g);
        }
    }
}

// ---------------- K_assign: dedup + targets + pos-max ----------------
__global__ __launch_bounds__(256) void k_assign(
    const float*  __restrict__ pd_scores,
    const int*    __restrict__ gt_labels,
    const float4* __restrict__ gt_bboxes,
    float* __restrict__ out)
{
    int b = blockIdx.y;
    __shared__ int s_lbl[NB];
    if (threadIdx.x < NB) s_lbl[threadIdx.x] = gt_labels[b*NB + threadIdx.x];
    __syncthreads();

    int a = blockIdx.x * 256 + threadIdx.x;
    if (a >= NA) return;
    int ba = b*NA + a;

    unsigned long long m = g_maskbits[ba];
    int fg = __popcll(m);
    int tgi = 0; float ovv = 0.f;
    if (fg > 1) {               // multi-assigned -> argmax over masked overlaps (all g)
        unsigned long long pk = g_pack[ba];
        if (pk) {
            tgi = 63 - (int)(pk & 63ull);
            ovv = __uint_as_float((unsigned)(pk >> 8));
        }
    } else if (fg == 1) {
        tgi = __ffsll((long long)m) - 1;
        unsigned long long ps = g_packsel[ba];
        ovv = __uint_as_float((unsigned)(ps >> 8));
    }
    bool active = fg > 0;

    float am = 0.f;
    if (active && ovv > 0.f) {
        float s = pd_scores[(long)ba * NC + s_lbl[tgi]];
        float o2 = ovv * ovv;
        am = s * o2 * o2 * o2;   // identical recompute of align metric
    }
    if (active) {   // non-negative floats: int-compare atomicMax is exact
        atomicMax((int*)&g_posalign[b*NB + tgi], __float_as_int(am));
        atomicMax((int*)&g_posover [b*NB + tgi], __float_as_int(ovv));
    }

    int lab = max(s_lbl[tgi], 0);
    g_tgi[ba] = tgi; g_fgb[ba] = active; g_amax[ba] = am; g_lab[ba] = lab;

    out[OFF_LABELS + ba] = (float)lab;
    ((float4*)(out + OFF_BBOX))[ba] = gt_bboxes[b*NB + tgi];
    out[OFF_FG  + ba] = active ? 1.f : 0.f;
    out[OFF_TGI + ba] = (float)tgi;
}

// ---------------- K_scores: single-pass full-row writer (zeros + one-hot value) ----------------
__global__ __launch_bounds__(256) void k_scores(float* __restrict__ out)
{
    int c0 = blockIdx.x * 128;            // 128 anchor-rows per block (BS*NA % 128 == 0)
    __shared__ float s_val[128];
    __shared__ int   s_lab[128];
    int t = threadIdx.x;
    if (t < 128) {
        int ba = c0 + t;
        float v = 0.f; int lab = 0;
        if (g_fgb[ba]) {
            int b = ba / NA;
            int tgi = g_tgi[ba];
            float pa = g_posalign[b*NB + tgi];
            float po = g_posover [b*NB + tgi];
            v = (g_amax[ba] * po) / (pa + 1e-9f);
            lab = g_lab[ba];
        }
        s_val[t] = v; s_lab[t] = lab;
    }
    __syncthreads();

    float4* dst = (float4*)(out + OFF_SCORES + (long)c0 * NC);
    const int T = 128 * NC / 4;           // 2560 float4 per block
    for (int i = t; i < T; i += 256) {
        int row = i / (NC/4);
        int q4  = (i % (NC/4)) * 4;
        float4 z = make_float4(0.f,0.f,0.f,0.f);
        int lab = s_lab[row];
        if (lab >= q4 && lab < q4 + 4)
            ((float*)&z)[lab - q4] = s_val[row];
        dst[i] = z;
    }
}

// ---------------- launch ----------------
extern "C" void kernel_launch(void* const* d_in, const int* in_sizes, int n_in,
                              void* d_out, int out_size)
{
    const float*  pd_scores = (const float*) d_in[0];
    const float4* pd_bboxes = (const float4*)d_in[1];
    const float2* anc       = (const float2*)d_in[2];
    const int*    gt_labels = (const int*)   d_in[3];
    const float4* gt_bboxes = (const float4*)d_in[4];
    const float*  mask_gt   = (const float*) d_in[5];
    float* out = (float*)d_out;

    dim3 gmain((NA + 255)/256, BS);
    k_main<<<gmain, 256>>>(pd_scores, pd_bboxes, anc, gt_labels, gt_bboxes, mask_gt);

    dim3 gtop(NB, BS);
    k_top<<<gtop, 32>>>(anc, gt_bboxes, mask_gt);

    dim3 gassign((NA + 255)/256, BS);
    k_assign<<<gassign, 256>>>(pd_scores, gt_labels, gt_bboxes, out);

    k_scores<<<(BS*NA)/128, 256>>>(out);
}

// round 12
// speedup vs baseline: 1.1796x; 1.0876x over previous
#include <cuda_runtime.h>
#include <math.h>

#define BS 32
#define NA 8400
#define NC 80
#define NB 64
#define TOPKK 13
#define CAP 512
#define GC 32                    // 32x32 grid of 20px cells over [0,640)
#define INV_CELL 0.05f

#define OFF_LABELS 0
#define OFF_BBOX   (BS*NA)
#define OFF_SCORES (BS*NA + BS*NA*4)
#define OFF_FG     (OFF_SCORES + BS*NA*NC)
#define OFF_TGI    (OFF_FG + BS*NA)

// ---------------- scratch ----------------
__device__ unsigned long long g_maskbits[BS*NA];  // bit g = mask_pos(g,a) pre-dedup
__device__ unsigned long long g_pack    [BS*NA];  // max over pairs: (ov_bits<<8)|(63-g)
__device__ unsigned long long g_packsel [BS*NA];  // same pack, topk-selected pairs only
__device__ float              g_posalign[BS*NB];
__device__ float              g_posover [BS*NB];
__device__ int                g_tgi [BS*NA];
__device__ unsigned char      g_fgb [BS*NA];
__device__ float              g_amax[BS*NA];
__device__ int                g_lab [BS*NA];
// anchor spatial grid (anc is batch-independent)
__device__ int    g_cellstart[GC*GC + 1];
__device__ float2 g_ga [NA];     // anchor positions, cell-sorted
__device__ int    g_gai[NA];     // anchor indices,   cell-sorted

__device__ __forceinline__ bool ap_inb(float4 G, float2 ap)
{
    return ap.x > G.x && ap.y > G.y && ap.x < G.z && ap.y < G.w;
}

__device__ __forceinline__ int cell_of(float v)
{
    return min(max((int)(v * INV_CELL), 0), GC - 1);
}

// ---------------- K_prep: block 0 builds the anchor grid; others clear scratch ----------------
__global__ __launch_bounds__(1024) void k_prep(const float2* __restrict__ anc)
{
    if (blockIdx.x == 0) {
        __shared__ int s_cnt[GC*GC];
        __shared__ int s_off[GC*GC];
        int t = threadIdx.x;                 // 1024 == GC*GC
        s_cnt[t] = 0;
        __syncthreads();
        for (int a = t; a < NA; a += 1024) {
            float2 ap = anc[a];
            atomicAdd(&s_cnt[cell_of(ap.y)*GC + cell_of(ap.x)], 1);
        }
        __syncthreads();
        int orig = s_cnt[t];
        // inclusive Hillis-Steele scan in place
        for (int d = 1; d < 1024; d <<= 1) {
            int u = (t >= d) ? s_cnt[t - d] : 0;
            __syncthreads();
            s_cnt[t] += u;
            __syncthreads();
        }
        int excl = s_cnt[t] - orig;
        g_cellstart[t] = excl;
        if (t == 1023) g_cellstart[1024] = s_cnt[1023];
        s_off[t] = excl;
        __syncthreads();
        for (int a = t; a < NA; a += 1024) {
            float2 ap = anc[a];
            int c = cell_of(ap.y)*GC + cell_of(ap.x);
            int pos = atomicAdd(&s_off[c], 1);
            g_ga[pos]  = ap;
            g_gai[pos] = a;
        }
    } else {
        long i = (long)(blockIdx.x - 1) * 1024 + threadIdx.x;
        const int NPA = BS*NA*8/16;          // 134400 int4 per u64 array
        int4 z = make_int4(0,0,0,0);
        if      (i <   NPA) ((int4*)g_maskbits)[i        ] = z;
        else if (i < 2*NPA) ((int4*)g_packsel )[i -   NPA] = z;
        else if (i < 3*NPA) ((int4*)g_pack    )[i - 2*NPA] = z;
        if (i < BS*NB) { g_posalign[i] = 0.f; g_posover[i] = 0.f; }
    }
}

// ---------------- K_rows: per-(b,g) grid-gather metric + top-13 + fill ----------------
__global__ __launch_bounds__(128) void k_rows(
    const float*  __restrict__ pd_scores,
    const float4* __restrict__ pd_bboxes,
    const float2* __restrict__ anc,
    const int*    __restrict__ gt_labels,
    const float4* __restrict__ gt_bboxes,
    const float*  __restrict__ mask_gt)
{
    int g = blockIdx.x, b = blockIdx.y;
    int row = b*NB + g;
    if (mask_gt[row] <= 0.f) return;   // masked rows contribute nothing

    __shared__ unsigned long long s_key[CAP];
    __shared__ float s_cov[CAP];
    __shared__ int   s_ca[CAP];
    __shared__ int   s_cnt;
    if (threadIdx.x == 0) s_cnt = 0;
    __syncthreads();

    float4 G = gt_bboxes[row];
    int lbl = gt_labels[row];
    float w1 = G.z - G.x, h1 = G.w - G.y + 1e-7f;
    float at1 = atanf(w1 / h1);
    float a1  = w1 * h1;

    const float4* pb = pd_bboxes + b*NA;
    const float*  sc = pd_scores + (long)b*NA*NC + lbl;

    int cx0 = cell_of(G.x), cx1 = cell_of(G.z);
    int cy0 = cell_of(G.y), cy1 = cell_of(G.w);

    for (int cy = cy0; cy <= cy1; ++cy) {
        int st = g_cellstart[cy*GC + cx0];
        int en = g_cellstart[cy*GC + cx1 + 1];   // contiguous cell-row slice
        for (int i = st + threadIdx.x; i < en; i += 128) {
            float2 ap = g_ga[i];
            if (!ap_inb(G, ap)) continue;        // strict in-box (== deltas.min > 1e-9)
            int a = g_gai[i];

            float4 p = pb[a];
            float iw = fminf(G.z, p.z) - fmaxf(G.x, p.x);
            float ih = fminf(G.w, p.w) - fmaxf(G.y, p.y);
            float inter = fmaxf(iw, 0.f) * fmaxf(ih, 0.f);
            float w2 = p.z - p.x, h2 = p.w - p.y + 1e-7f;
            float uni = a1 + w2*h2 - inter + 1e-7f;
            float iou = inter / uni;
            float cw = fmaxf(G.z, p.z) - fminf(G.x, p.x);
            float ch = fmaxf(G.w, p.w) - fminf(G.y, p.y);
            float c2 = cw*cw + ch*ch + 1e-7f;
            float dx = p.x + p.z - G.x - G.z;
            float dy = p.y + p.w - G.y - G.w;
            float rho2 = (dx*dx + dy*dy) * 0.25f;
            float dd = atanf(w2 / h2) - at1;
            float v = 0.4052847345693511f * dd * dd;   // 4/pi^2
            float alpha = v / (v - iou + (1.0f + 1e-7f));
            float ci = iou - (rho2 / c2 + v * alpha);
            float ov = fmaxf(ci, 0.f);
            if (ov <= 0.f) continue;

            // per-anchor argmax over g (ties -> lowest g, like jnp.argmax)
            unsigned long long pk =
                ((unsigned long long)__float_as_uint(ov) << 8) | (unsigned)(63 - g);
            atomicMax(&g_pack[b*NA + a], pk);

            float s  = sc[a * NC];
            float o2 = ov * ov;
            float al = s * o2 * o2 * o2;   // score^1 * ov^6
            if (al > 0.f) {
                int slot = atomicAdd(&s_cnt, 1);
                if (slot < CAP) {
                    s_key[slot] = ((unsigned long long)__float_as_uint(al) << 32)
                                | (unsigned)(NA - 1 - a);
                    s_cov[slot] = ov;
                    s_ca[slot]  = a;
                }
            }
        }
    }
    __syncthreads();

    // warp 0: top-13 (ties -> lowest anchor index; keys are a total order)
    if (threadIdx.x < 32) {
        int lane = threadIdx.x;
        int C = min(s_cnt, CAP);
        int npos = min(C, TOPKK);
        for (int it = 0; it < npos; ++it) {
            unsigned long long bk = 0; int bj = -1;
            for (int j = lane; j < C; j += 32) {
                unsigned long long k = s_key[j];
                if (k > bk) { bk = k; bj = j; }
            }
            #pragma unroll
            for (int off = 16; off; off >>= 1) {
                unsigned long long kk = __shfl_down_sync(0xffffffffu, bk, off);
                int jj = __shfl_down_sync(0xffffffffu, bj, off);
                if (kk > bk) { bk = kk; bj = jj; }
            }
            bj = __shfl_sync(0xffffffffu, bj, 0);
            if (lane == 0) {
                int a = s_ca[bj];
                atomicOr(&g_maskbits[b*NA + a], 1ull << g);  // positives are in-box
                unsigned long long pk =
                    ((unsigned long long)__float_as_uint(s_cov[bj]) << 8) | (unsigned)(63 - g);
                atomicMax(&g_packsel[b*NA + a], pk);
                s_key[bj] = 0;
            }
            __syncwarp();
        }
        // fewer than 13 positives: ref fills with lowest-index zero entries
        if (lane == 0 && C < TOPKK) {
            int rem = TOPKK - C;
            for (int a = 0; rem > 0 && a < NA; ++a) {
                bool member = false;
                for (int j = 0; j < C; ++j) if (s_ca[j] == a) { member = true; break; }
                if (member) continue;
                rem--;                              // slot consumed by this zero entry
                if (ap_inb(G, anc[a]))              // mask only if in-box (ov=0 -> no packsel)
                    atomicOr(&g_maskbits[b*NA + a], 1ull << g);
            }
        }
    }
}

// ---------------- K_assign: dedup + targets + pos-max ----------------
__global__ __launch_bounds__(256) void k_assign(
    const float*  __restrict__ pd_scores,
    const int*    __restrict__ gt_labels,
    const float4* __restrict__ gt_bboxes,
    float* __restrict__ out)
{
    int b = blockIdx.y;
    __shared__ int s_lbl[NB];
    if (threadIdx.x < NB) s_lbl[threadIdx.x] = gt_labels[b*NB + threadIdx.x];
    __syncthreads();

    int a = blockIdx.x * 256 + threadIdx.x;
    if (a >= NA) return;
    int ba = b*NA + a;

    unsigned long long m = g_maskbits[ba];
    int fg = __popcll(m);
    int tgi = 0; float ovv = 0.f;
    if (fg > 1) {               // multi-assigned -> argmax over masked overlaps (all g)
        unsigned long long pk = g_pack[ba];
        if (pk) {
            tgi = 63 - (int)(pk & 63ull);
            ovv = __uint_as_float((unsigned)(pk >> 8));
        }
    } else if (fg == 1) {
        tgi = __ffsll((long long)m) - 1;
        unsigned long long ps = g_packsel[ba];
        ovv = __uint_as_float((unsigned)(ps >> 8));
    }
    bool active = fg > 0;

    float am = 0.f;
    if (active && ovv > 0.f) {
        float s = pd_scores[(long)ba * NC + s_lbl[tgi]];
        float o2 = ovv * ovv;
        am = s * o2 * o2 * o2;   // identical recompute of align metric
    }
    if (active) {   // non-negative floats: int-compare atomicMax is exact
        atomicMax((int*)&g_posalign[b*NB + tgi], __float_as_int(am));
        atomicMax((int*)&g_posover [b*NB + tgi], __float_as_int(ovv));
    }

    int lab = max(s_lbl[tgi], 0);
    g_tgi[ba] = tgi; g_fgb[ba] = active; g_amax[ba] = am; g_lab[ba] = lab;

    out[OFF_LABELS + ba] = (float)lab;
    ((float4*)(out + OFF_BBOX))[ba] = gt_bboxes[b*NB + tgi];
    out[OFF_FG  + ba] = active ? 1.f : 0.f;
    out[OFF_TGI + ba] = (float)tgi;
}

// ---------------- K_scores: unconditional zero-fill + sparse one-hot scatter ----------------
__global__ __launch_bounds__(256) void k_scores(float* __restrict__ out)
{
    int c0 = blockIdx.x * 128;            // 128 anchor-rows per block
    float4* dst = (float4*)(out + OFF_SCORES + (long)c0 * NC);
    float4 z = make_float4(0.f,0.f,0.f,0.f);
    #pragma unroll
    for (int i = threadIdx.x; i < 128 * NC / 4; i += 256)
        dst[i] = z;                       // pure streaming stores, no bookkeeping
    __syncthreads();                      // orders block's zero writes before scatter

    int t = threadIdx.x;
    if (t < 128) {
        int ba = c0 + t;
        if (g_fgb[ba]) {
            int b = ba / NA;
            int tgi = g_tgi[ba];
            float pa = g_posalign[b*NB + tgi];
            float po = g_posover [b*NB + tgi];
            out[OFF_SCORES + (long)ba * NC + g_lab[ba]] =
                (g_amax[ba] * po) / (pa + 1e-9f);
        }
    }
}

// ---------------- launch ----------------
extern "C" void kernel_launch(void* const* d_in, const int* in_sizes, int n_in,
                              void* d_out, int out_size)
{
    const float*  pd_scores = (const float*) d_in[0];
    const float4* pd_bboxes = (const float4*)d_in[1];
    const float2* anc       = (const float2*)d_in[2];
    const int*    gt_labels = (const int*)   d_in[3];
    const float4* gt_bboxes = (const float4*)d_in[4];
    const float*  mask_gt   = (const float*) d_in[5];
    float* out = (float*)d_out;

    const int NPA = BS*NA*8/16;
    k_prep<<<1 + (3*NPA + 1023)/1024, 1024>>>(anc);

    dim3 grows(NB, BS);
    k_rows<<<grows, 128>>>(pd_scores, pd_bboxes, anc, gt_labels, gt_bboxes, mask_gt);

    dim3 gassign((NA + 255)/256, BS);
    k_assign<<<gassign, 256>>>(pd_scores, gt_labels, gt_bboxes, out);

    k_scores<<<(BS*NA)/128, 256>>>(out);
}